// round 2
// baseline (speedup 1.0000x reference)
#include <cuda_runtime.h>
#include <math.h>

// Problem constants (fixed by setup_inputs): B=2, N=6890, NF=2000
#define B_    2
#define NMAX  7168
#define NFMAX 2048
#define WCH   8        // triangle chunks for winding
#define MCH   8        // point chunks for minsq
#define BIGF  3.4e38f

// -------- device scratch (no allocations allowed) --------
// points as float4 (x,y,z,|p|^2): [cloud][b*N+n]
__device__ float4 g_pts4[2][B_ * NMAX];
// gathered triangles, 3 float4 per tri: [Ax,Ay,Az,Bx][By,Bz,Cx,Cy][Cz,0,0,0]
__device__ float4 g_tri4[2][B_ * NFMAX * 3];
// partial atan2 sums: [chunk][seg*NMAX + n], seg = dir*2 + b
__device__ float g_wpart[WCH][4 * NMAX];
// partial (|q|^2 - 2 p.q + |p|^2) mins: [chunk][seg*NMAX + n]
__device__ float g_mpart[MCH][4 * NMAX];

// ---------------------------------------------------------
// fast atan2: minimax odd polynomial on [0,1], abs err ~6e-7
// ---------------------------------------------------------
__device__ __forceinline__ float fast_atan2f(float y, float x) {
    float ax = fabsf(x), ay = fabsf(y);
    float mx = fmaxf(ax, ay);
    float mn = fminf(ax, ay);
    if (mx == 0.0f) return 0.0f;
    float t = __fdividef(mn, mx);
    float s = t * t;
    float p = fmaf(s, -0.01172120f, 0.05265332f);
    p = fmaf(s, p, -0.11643287f);
    p = fmaf(s, p,  0.19354346f);
    p = fmaf(s, p, -0.33262347f);
    p = fmaf(s, p,  0.99997726f);
    float r = p * t;
    if (ay > ax)  r = 1.57079632679f - r;
    if (x < 0.0f) r = 3.14159265359f - r;
    return (y < 0.0f) ? -r : r;
}

// solid angle contribution: atan2 term (un-doubled, un-normalized)
__device__ __forceinline__ float solid_term(
    float px, float py, float pz,
    float Ax, float Ay, float Az,
    float Bx, float By, float Bz,
    float Cx, float Cy, float Cz)
{
    float ax = Ax - px, ay = Ay - py, az = Az - pz;
    float bx = Bx - px, by = By - py, bz = Bz - pz;
    float cx = Cx - px, cy = Cy - py, cz = Cz - pz;

    float a2 = fmaf(ax, ax, fmaf(ay, ay, az * az));
    float b2 = fmaf(bx, bx, fmaf(by, by, bz * bz));
    float c2 = fmaf(cx, cx, fmaf(cy, cy, cz * cz));
    float la = a2 * rsqrtf(a2);
    float lb = b2 * rsqrtf(b2);
    float lc = c2 * rsqrtf(c2);

    float crx = fmaf(by, cz, -bz * cy);
    float cry = fmaf(bz, cx, -bx * cz);
    float crz = fmaf(bx, cy, -by * cx);
    float det = fmaf(ax, crx, fmaf(ay, cry, az * crz));

    float dab = fmaf(ax, bx, fmaf(ay, by, az * bz));
    float dbc = fmaf(bx, cx, fmaf(by, cy, bz * cz));
    float dca = fmaf(cx, ax, fmaf(cy, ay, cz * az));

    float denom = fmaf(la * lb, lc, fmaf(dab, lc, fmaf(dbc, la, dca * lb)));
    return fast_atan2f(det, denom);
}

// ---------------------------------------------------------
// gather: float4 point arrays (with |p|^2) + packed triangle soup
// ---------------------------------------------------------
__global__ void gather_kernel(const float* __restrict__ v1,
                              const float* __restrict__ v2,
                              const int*   __restrict__ faces,
                              int N, int NF) {
    int stride = gridDim.x * blockDim.x;
    int t0 = blockIdx.x * blockDim.x + threadIdx.x;

    int PT = B_ * N;
    for (int i = t0; i < PT; i += stride) {
        float x = v1[i * 3 + 0], y = v1[i * 3 + 1], z = v1[i * 3 + 2];
        g_pts4[0][i] = make_float4(x, y, z, fmaf(x, x, fmaf(y, y, z * z)));
        x = v2[i * 3 + 0]; y = v2[i * 3 + 1]; z = v2[i * 3 + 2];
        g_pts4[1][i] = make_float4(x, y, z, fmaf(x, x, fmaf(y, y, z * z)));
    }

    int FT = B_ * NF;
    for (int i = t0; i < FT; i += stride) {
        int b = i / NF;
        int f = i - b * NF;
        int i0 = faces[f * 3 + 0];
        int i1 = faces[f * 3 + 1];
        int i2 = faces[f * 3 + 2];
        int base = b * N * 3;
        #pragma unroll
        for (int s = 0; s < 2; s++) {
            const float* v = (s == 0) ? v1 : v2;
            float Ax = v[base + i0 * 3 + 0], Ay = v[base + i0 * 3 + 1], Az = v[base + i0 * 3 + 2];
            float Bx = v[base + i1 * 3 + 0], By = v[base + i1 * 3 + 1], Bz = v[base + i1 * 3 + 2];
            float Cx = v[base + i2 * 3 + 0], Cy = v[base + i2 * 3 + 1], Cz = v[base + i2 * 3 + 2];
            g_tri4[s][i * 3 + 0] = make_float4(Ax, Ay, Az, Bx);
            g_tri4[s][i * 3 + 1] = make_float4(By, Bz, Cx, Cy);
            g_tri4[s][i * 3 + 2] = make_float4(Cz, 0.0f, 0.0f, 0.0f);
        }
    }
}

// ---------------------------------------------------------
// winding: 2 points per thread, warp-uniform triangle loop (broadcast loads)
// grid: x covers H=ceil(N/2) threads, y = seg*WCH + chunk  (seg = dir*2+b)
// ---------------------------------------------------------
__global__ void __launch_bounds__(256)
winding_kernel(int N, int NF) {
    int yc = blockIdx.y;
    int seg = yc >> 3;          // dir*2 + b
    int chunk = yc & 7;
    int dir = seg >> 1;
    int b = seg & 1;
    int H = (N + 1) >> 1;
    int t = blockIdx.x * 256 + threadIdx.x;
    if (t >= H) return;

    int src = 1 - dir;
    int fpc = (NF + WCH - 1) / WCH;
    int f0 = chunk * fpc;
    int f1 = min(NF, f0 + fpc);

    const float4* __restrict__ P = g_pts4[dir] + b * N;
    int i0 = t, i1 = t + H;
    bool ok1 = (i1 < N);
    float4 p0 = P[i0];
    float4 p1 = ok1 ? P[i1] : p0;

    const float4* __restrict__ T = g_tri4[src] + (size_t)(b * NF) * 3;

    float acc0 = 0.0f, acc1 = 0.0f;
    for (int f = f0; f < f1; ++f) {
        float4 q0 = T[f * 3 + 0];
        float4 q1 = T[f * 3 + 1];
        float4 q2 = T[f * 3 + 2];
        float Ax = q0.x, Ay = q0.y, Az = q0.z;
        float Bx = q0.w, By = q1.x, Bz = q1.y;
        float Cx = q1.z, Cy = q1.w, Cz = q2.x;
        acc0 += solid_term(p0.x, p0.y, p0.z, Ax, Ay, Az, Bx, By, Bz, Cx, Cy, Cz);
        acc1 += solid_term(p1.x, p1.y, p1.z, Ax, Ay, Az, Bx, By, Bz, Cx, Cy, Cz);
    }
    int base = seg * NMAX;
    g_wpart[chunk][base + i0] = acc0;
    if (ok1) g_wpart[chunk][base + i1] = acc1;
}

// ---------------------------------------------------------
// minsq: 4 points per thread, warp-uniform loop over other cloud
// grid: x covers Q=ceil(N/4) threads, y = seg*MCH + chunk
// stores min over chunk of (|p|^2 + |q|^2 - 2 p.q)
// ---------------------------------------------------------
__global__ void __launch_bounds__(256)
minsq_kernel(int N) {
    int yc = blockIdx.y;
    int seg = yc >> 3;
    int chunk = yc & 7;
    int dir = seg >> 1;
    int b = seg & 1;
    int Q = (N + 3) >> 2;
    int t = blockIdx.x * 256 + threadIdx.x;
    if (t >= Q) return;

    const float4* __restrict__ P = g_pts4[dir] + b * N;
    const float4* __restrict__ O = g_pts4[1 - dir] + b * N;

    int i0 = t, i1 = t + Q, i2 = t + 2 * Q, i3 = t + 3 * Q;
    bool ok1 = (i1 < N), ok2 = (i2 < N), ok3 = (i3 < N);
    float4 p0 = P[i0];
    float4 p1 = ok1 ? P[i1] : p0;
    float4 p2 = ok2 ? P[i2] : p0;
    float4 p3 = ok3 ? P[i3] : p0;

    int mpc = (N + MCH - 1) / MCH;
    int m0 = chunk * mpc;
    int m1 = min(N, m0 + mpc);

    float b0 = BIGF, b1v = BIGF, b2v = BIGF, b3v = BIGF;
    for (int m = m0; m < m1; ++m) {
        float4 q = O[m];
        float d0 = fmaf(p0.x, q.x, fmaf(p0.y, q.y, p0.z * q.z));
        float d1 = fmaf(p1.x, q.x, fmaf(p1.y, q.y, p1.z * q.z));
        float d2 = fmaf(p2.x, q.x, fmaf(p2.y, q.y, p2.z * q.z));
        float d3 = fmaf(p3.x, q.x, fmaf(p3.y, q.y, p3.z * q.z));
        b0  = fminf(b0,  fmaf(-2.0f, d0, q.w));
        b1v = fminf(b1v, fmaf(-2.0f, d1, q.w));
        b2v = fminf(b2v, fmaf(-2.0f, d2, q.w));
        b3v = fminf(b3v, fmaf(-2.0f, d3, q.w));
    }
    int base = seg * NMAX;
    g_mpart[chunk][base + i0] = b0 + p0.w;
    if (ok1) g_mpart[chunk][base + i1] = b1v + p1.w;
    if (ok2) g_mpart[chunk][base + i2] = b2v + p2.w;
    if (ok3) g_mpart[chunk][base + i3] = b3v + p3.w;
}

// ---------------------------------------------------------
// finalize: parallel reduction. One block per batch b.
// out layout: [5][B] row-major
// ---------------------------------------------------------
__global__ void __launch_bounds__(256)
finalize_kernel(float* __restrict__ out, int N) {
    __shared__ float sh[8][7];
    const float INV2PI = 0.15915494309189535f;
    int b = blockIdx.x;
    int tid = threadIdx.x;
    int lane = tid & 31;
    int warp = tid >> 5;

    float mn = BIGF;
    float mx1 = -BIGF, s1 = 0.0f, c1 = 0.0f;
    float mx2 = -BIGF, s2 = 0.0f, c2 = 0.0f;

    int seg0 = b;        // dir 0
    int seg1 = 2 + b;    // dir 1

    for (int n = tid; n < N; n += 256) {
        int ia = seg0 * NMAX + n;
        float w = 0.0f, ms = BIGF;
        #pragma unroll
        for (int c = 0; c < WCH; c++) {
            w += g_wpart[c][ia];
            ms = fminf(ms, g_mpart[c][ia]);
        }
        float rm = sqrtf(fmaxf(ms, 0.0f));
        mn = fminf(mn, rm);
        if (w * INV2PI >= 0.99f) { mx1 = fmaxf(mx1, rm); s1 += rm; c1 += 1.0f; }

        int ib = seg1 * NMAX + n;
        float w2 = 0.0f, ms2 = BIGF;
        #pragma unroll
        for (int c = 0; c < WCH; c++) {
            w2 += g_wpart[c][ib];
            ms2 = fminf(ms2, g_mpart[c][ib]);
        }
        float cmv = sqrtf(fmaxf(ms2, 0.0f));
        if (w2 * INV2PI >= 0.99f) { mx2 = fmaxf(mx2, cmv); s2 += cmv; c2 += 1.0f; }
    }

    #pragma unroll
    for (int o = 16; o; o >>= 1) {
        mn  = fminf(mn,  __shfl_xor_sync(0xffffffffu, mn,  o));
        mx1 = fmaxf(mx1, __shfl_xor_sync(0xffffffffu, mx1, o));
        s1 +=            __shfl_xor_sync(0xffffffffu, s1,  o);
        c1 +=            __shfl_xor_sync(0xffffffffu, c1,  o);
        mx2 = fmaxf(mx2, __shfl_xor_sync(0xffffffffu, mx2, o));
        s2 +=            __shfl_xor_sync(0xffffffffu, s2,  o);
        c2 +=            __shfl_xor_sync(0xffffffffu, c2,  o);
    }
    if (lane == 0) {
        sh[warp][0] = mn;  sh[warp][1] = mx1; sh[warp][2] = s1; sh[warp][3] = c1;
        sh[warp][4] = mx2; sh[warp][5] = s2;  sh[warp][6] = c2;
    }
    __syncthreads();
    if (tid == 0) {
        mn = sh[0][0]; mx1 = sh[0][1]; s1 = sh[0][2]; c1 = sh[0][3];
        mx2 = sh[0][4]; s2 = sh[0][5]; c2 = sh[0][6];
        #pragma unroll
        for (int w = 1; w < 8; w++) {
            mn  = fminf(mn,  sh[w][0]);
            mx1 = fmaxf(mx1, sh[w][1]);
            s1 += sh[w][2];  c1 += sh[w][3];
            mx2 = fmaxf(mx2, sh[w][4]);
            s2 += sh[w][5];  c2 += sh[w][6];
        }
        out[0 * B_ + b] = mn;
        out[1 * B_ + b] = (c1 > 0.0f) ? mx1 : 0.0f;
        out[2 * B_ + b] = (c1 > 0.0f) ? s1 / fmaxf(c1, 1.0f) : 0.0f;
        out[3 * B_ + b] = (c2 > 0.0f) ? mx2 : 0.0f;
        out[4 * B_ + b] = (c2 > 0.0f) ? s2 / fmaxf(c2, 1.0f) : 0.0f;
    }
}

// ---------------------------------------------------------
extern "C" void kernel_launch(void* const* d_in, const int* in_sizes, int n_in,
                              void* d_out, int out_size) {
    const float* v1 = (const float*)d_in[0];
    const float* v2 = (const float*)d_in[1];
    const int* faces = (const int*)d_in[2];
    float* out = (float*)d_out;

    int N = in_sizes[0] / (3 * B_);   // 6890
    int NF = in_sizes[2] / 3;         // 2000

    int gwork = B_ * N;
    if (B_ * NF > gwork) gwork = B_ * NF;
    gather_kernel<<<(gwork + 255) / 256, 256>>>(v1, v2, faces, N, NF);

    int H = (N + 1) >> 1;                         // points per thread-pair slot
    dim3 wgrid((H + 255) / 256, 4 * WCH);         // 4 segs x 8 chunks
    winding_kernel<<<wgrid, 256>>>(N, NF);

    int Q = (N + 3) >> 2;
    dim3 mgrid((Q + 255) / 256, 4 * MCH);
    minsq_kernel<<<mgrid, 256>>>(N);

    finalize_kernel<<<B_, 256>>>(out, N);
}

// round 3
// speedup vs baseline: 1.3658x; 1.3658x over previous
#include <cuda_runtime.h>
#include <math.h>

// Problem constants (fixed by setup_inputs): B=2, N=6890, NF=2000
#define B_    2
#define NMAX  7168
#define NFMAX 2048
#define WCH   8        // triangle chunks for winding
#define MCH   8        // point chunks for minsq
#define NB1   32       // stage-1 reduce blocks per segment
#define BIGF  3.4e38f

typedef unsigned long long ull;

// -------- device scratch (no allocations allowed) --------
// points as float4 (x,y,z,|p|^2): [cloud][b*N+n]
__device__ float4 g_pts4[2][B_ * NMAX];
// triangles: A+nx, B+ny, C+nz packed; d0 = A.n separate
__device__ float4 g_triA[2][B_ * NFMAX];
__device__ float4 g_triB[2][B_ * NFMAX];
__device__ float4 g_triC[2][B_ * NFMAX];
__device__ float  g_trid[2][B_ * NFMAX];
// partial atan2 sums: [chunk][seg*NMAX + n], seg = dir*2 + b
__device__ float g_wpart[WCH][4 * NMAX];
// partial (|q|^2 - 2 p.q + |p|^2) mins: [chunk][seg*NMAX + n]
__device__ float g_mpart[MCH][4 * NMAX];
// stage-1 reduction partials: [seg][block] = (mn, mx, sum, cnt)
__device__ float4 g_red[4][NB1];

// ---------------- packed f32x2 helpers (sm_100+) ----------------
__device__ __forceinline__ ull pk2(float lo, float hi) {
    ull r;
    asm("mov.b64 %0, {%1, %2};" : "=l"(r)
        : "r"(__float_as_uint(lo)), "r"(__float_as_uint(hi)));
    return r;
}
__device__ __forceinline__ ull bc2(float v) { return pk2(v, v); }
__device__ __forceinline__ float2 unpk2(ull v) {
    unsigned int lo, hi;
    asm("mov.b64 {%0, %1}, %2;" : "=r"(lo), "=r"(hi) : "l"(v));
    return make_float2(__uint_as_float(lo), __uint_as_float(hi));
}
__device__ __forceinline__ ull fma2(ull a, ull b, ull c) {
    ull d; asm("fma.rn.f32x2 %0, %1, %2, %3;" : "=l"(d) : "l"(a), "l"(b), "l"(c)); return d;
}
__device__ __forceinline__ ull add2(ull a, ull b) {
    ull d; asm("add.rn.f32x2 %0, %1, %2;" : "=l"(d) : "l"(a), "l"(b)); return d;
}
__device__ __forceinline__ ull mul2(ull a, ull b) {
    ull d; asm("mul.rn.f32x2 %0, %1, %2;" : "=l"(d) : "l"(a), "l"(b)); return d;
}
__device__ __forceinline__ float sqrt_ap(float x) {
    float r; asm("sqrt.approx.f32 %0, %1;" : "=f"(r) : "f"(x)); return r;
}

// ---------------------------------------------------------
// fast atan2: minimax odd polynomial on [0,1], abs err ~6e-7
// ---------------------------------------------------------
__device__ __forceinline__ float fast_atan2f(float y, float x) {
    float ax = fabsf(x), ay = fabsf(y);
    float mx = fmaxf(ax, ay);
    float mn = fminf(ax, ay);
    if (mx == 0.0f) return 0.0f;
    float t = __fdividef(mn, mx);
    float s = t * t;
    float p = fmaf(s, -0.01172120f, 0.05265332f);
    p = fmaf(s, p, -0.11643287f);
    p = fmaf(s, p,  0.19354346f);
    p = fmaf(s, p, -0.33262347f);
    p = fmaf(s, p,  0.99997726f);
    float r = p * t;
    if (ay > ax)  r = 1.57079632679f - r;
    if (x < 0.0f) r = 3.14159265359f - r;
    return (y < 0.0f) ? -r : r;
}

// ---------------------------------------------------------
// gather: float4 points (with |p|^2), triangles + normal + d0
// ---------------------------------------------------------
__global__ void gather_kernel(const float* __restrict__ v1,
                              const float* __restrict__ v2,
                              const int*   __restrict__ faces,
                              int N, int NF) {
    int stride = gridDim.x * blockDim.x;
    int t0 = blockIdx.x * blockDim.x + threadIdx.x;

    int PT = B_ * N;
    for (int i = t0; i < PT; i += stride) {
        float x = v1[i * 3 + 0], y = v1[i * 3 + 1], z = v1[i * 3 + 2];
        g_pts4[0][i] = make_float4(x, y, z, fmaf(x, x, fmaf(y, y, z * z)));
        x = v2[i * 3 + 0]; y = v2[i * 3 + 1]; z = v2[i * 3 + 2];
        g_pts4[1][i] = make_float4(x, y, z, fmaf(x, x, fmaf(y, y, z * z)));
    }

    int FT = B_ * NF;
    for (int i = t0; i < FT; i += stride) {
        int b = i / NF;
        int f = i - b * NF;
        int i0 = faces[f * 3 + 0];
        int i1 = faces[f * 3 + 1];
        int i2 = faces[f * 3 + 2];
        int base = b * N * 3;
        #pragma unroll
        for (int s = 0; s < 2; s++) {
            const float* v = (s == 0) ? v1 : v2;
            float Ax = v[base + i0 * 3 + 0], Ay = v[base + i0 * 3 + 1], Az = v[base + i0 * 3 + 2];
            float Bx = v[base + i1 * 3 + 0], By = v[base + i1 * 3 + 1], Bz = v[base + i1 * 3 + 2];
            float Cx = v[base + i2 * 3 + 0], Cy = v[base + i2 * 3 + 1], Cz = v[base + i2 * 3 + 2];
            float ex = Bx - Ax, ey = By - Ay, ez = Bz - Az;
            float fx = Cx - Ax, fy = Cy - Ay, fz = Cz - Az;
            float nx = fmaf(ey, fz, -ez * fy);
            float ny = fmaf(ez, fx, -ex * fz);
            float nz = fmaf(ex, fy, -ey * fx);
            float d0 = fmaf(Ax, nx, fmaf(Ay, ny, Az * nz));
            g_triA[s][i] = make_float4(Ax, Ay, Az, nx);
            g_triB[s][i] = make_float4(Bx, By, Bz, ny);
            g_triC[s][i] = make_float4(Cx, Cy, Cz, nz);
            g_trid[s][i] = d0;
        }
    }
}

// ---------------------------------------------------------
// winding: 2 points per thread packed in f32x2 lanes,
// warp-uniform triangle loop (broadcast loads).
// grid: x covers H=ceil(N/2) threads, y = seg*WCH + chunk (seg = dir*2+b)
// ---------------------------------------------------------
__global__ void __launch_bounds__(256, 2)
winding_kernel(int N, int NF) {
    int yc = blockIdx.y;
    int seg = yc >> 3;          // dir*2 + b
    int chunk = yc & 7;
    int dir = seg >> 1;
    int b = seg & 1;
    int H = (N + 1) >> 1;
    int t = blockIdx.x * 256 + threadIdx.x;
    if (t >= H) return;

    int src = 1 - dir;
    int fpc = (NF + WCH - 1) / WCH;
    int f0 = chunk * fpc;
    int f1 = min(NF, f0 + fpc);

    const float4* __restrict__ P = g_pts4[dir] + b * N;
    int i0 = t, i1 = t + H;
    bool ok1 = (i1 < N);
    float4 p0 = P[i0];
    float4 p1 = ok1 ? P[i1] : p0;

    // packed negated point coords
    ull npx = pk2(-p0.x, -p1.x);
    ull npy = pk2(-p0.y, -p1.y);
    ull npz = pk2(-p0.z, -p1.z);

    int tb = b * NF;
    const float4* __restrict__ TA = g_triA[src] + tb;
    const float4* __restrict__ TB = g_triB[src] + tb;
    const float4* __restrict__ TC = g_triC[src] + tb;
    const float*  __restrict__ TD = g_trid[src] + tb;

    float acc0 = 0.0f, acc1 = 0.0f;
    for (int f = f0; f < f1; ++f) {
        float4 tA = TA[f];   // Ax,Ay,Az,nx
        float4 tB = TB[f];   // Bx,By,Bz,ny
        float4 tC = TC[f];   // Cx,Cy,Cz,nz
        float d0v = TD[f];

        ull ax = add2(bc2(tA.x), npx);
        ull ay = add2(bc2(tA.y), npy);
        ull az = add2(bc2(tA.z), npz);
        ull bx = add2(bc2(tB.x), npx);
        ull by = add2(bc2(tB.y), npy);
        ull bz = add2(bc2(tB.z), npz);
        ull cx = add2(bc2(tC.x), npx);
        ull cy = add2(bc2(tC.y), npy);
        ull cz = add2(bc2(tC.z), npz);

        ull a2 = fma2(ax, ax, fma2(ay, ay, mul2(az, az)));
        ull b2 = fma2(bx, bx, fma2(by, by, mul2(bz, bz)));
        ull c2 = fma2(cx, cx, fma2(cy, cy, mul2(cz, cz)));

        // det = d0 - p.n = d0 + np.n
        ull det = add2(bc2(d0v),
                   fma2(npx, bc2(tA.w),
                   fma2(npy, bc2(tB.w),
                   mul2(npz, bc2(tC.w)))));

        ull dab = fma2(ax, bx, fma2(ay, by, mul2(az, bz)));
        ull dbc = fma2(bx, cx, fma2(by, cy, mul2(bz, cz)));
        ull dca = fma2(cx, ax, fma2(cy, ay, mul2(cz, az)));

        float2 a2s = unpk2(a2), b2s = unpk2(b2), c2s = unpk2(c2);
        float2 dets = unpk2(det);
        float2 dabs = unpk2(dab), dbcs = unpk2(dbc), dcas = unpk2(dca);

        float la0 = sqrt_ap(a2s.x), lb0 = sqrt_ap(b2s.x), lc0 = sqrt_ap(c2s.x);
        float la1 = sqrt_ap(a2s.y), lb1 = sqrt_ap(b2s.y), lc1 = sqrt_ap(c2s.y);

        float den0 = fmaf(la0 * lb0, lc0, fmaf(dabs.x, lc0, fmaf(dbcs.x, la0, dcas.x * lb0)));
        float den1 = fmaf(la1 * lb1, lc1, fmaf(dabs.y, lc1, fmaf(dbcs.y, la1, dcas.y * lb1)));

        acc0 += fast_atan2f(dets.x, den0);
        acc1 += fast_atan2f(dets.y, den1);
    }
    int base = seg * NMAX;
    g_wpart[chunk][base + i0] = acc0;
    if (ok1) g_wpart[chunk][base + i1] = acc1;
}

// ---------------------------------------------------------
// minsq: 4 scalar points per thread vs packed pairs of q.
// grid: x covers Q=ceil(N/4) threads, y = seg*MCH + chunk
// stores min over chunk of (|p|^2 + |q|^2 - 2 p.q)
// ---------------------------------------------------------
__global__ void __launch_bounds__(256, 2)
minsq_kernel(int N) {
    int yc = blockIdx.y;
    int seg = yc >> 3;
    int chunk = yc & 7;
    int dir = seg >> 1;
    int b = seg & 1;
    int Q = (N + 3) >> 2;
    int t = blockIdx.x * 256 + threadIdx.x;
    if (t >= Q) return;

    const float4* __restrict__ P = g_pts4[dir] + b * N;
    const float4* __restrict__ O = g_pts4[1 - dir] + b * N;

    int i0 = t, i1 = t + Q, i2 = t + 2 * Q, i3 = t + 3 * Q;
    bool ok1 = (i1 < N), ok2 = (i2 < N), ok3 = (i3 < N);
    float4 p0 = P[i0];
    float4 p1 = ok1 ? P[i1] : p0;
    float4 p2 = ok2 ? P[i2] : p0;
    float4 p3 = ok3 ? P[i3] : p0;

    // hoisted packed broadcasts of point coords
    ull p0x = bc2(p0.x), p0y = bc2(p0.y), p0z = bc2(p0.z);
    ull p1x = bc2(p1.x), p1y = bc2(p1.y), p1z = bc2(p1.z);
    ull p2x = bc2(p2.x), p2y = bc2(p2.y), p2z = bc2(p2.z);
    ull p3x = bc2(p3.x), p3y = bc2(p3.y), p3z = bc2(p3.z);
    ull m2  = bc2(-2.0f);

    int mpc = (N + MCH - 1) / MCH;
    int m0 = chunk * mpc;
    int m1 = min(N, m0 + mpc);

    float b0 = BIGF, b1v = BIGF, b2v = BIGF, b3v = BIGF;
    int m = m0;
    for (; m + 1 < m1; m += 2) {
        float4 qa = O[m];
        float4 qb = O[m + 1];
        ull qx = pk2(qa.x, qb.x);
        ull qy = pk2(qa.y, qb.y);
        ull qz = pk2(qa.z, qb.z);
        ull qw = pk2(qa.w, qb.w);

        ull d0 = fma2(p0x, qx, fma2(p0y, qy, mul2(p0z, qz)));
        ull d1 = fma2(p1x, qx, fma2(p1y, qy, mul2(p1z, qz)));
        ull d2 = fma2(p2x, qx, fma2(p2y, qy, mul2(p2z, qz)));
        ull d3 = fma2(p3x, qx, fma2(p3y, qy, mul2(p3z, qz)));
        float2 v0 = unpk2(fma2(m2, d0, qw));
        float2 v1 = unpk2(fma2(m2, d1, qw));
        float2 v2 = unpk2(fma2(m2, d2, qw));
        float2 v3 = unpk2(fma2(m2, d3, qw));
        b0  = fminf(b0,  fminf(v0.x, v0.y));
        b1v = fminf(b1v, fminf(v1.x, v1.y));
        b2v = fminf(b2v, fminf(v2.x, v2.y));
        b3v = fminf(b3v, fminf(v3.x, v3.y));
    }
    for (; m < m1; ++m) {
        float4 q = O[m];
        float d0 = fmaf(p0.x, q.x, fmaf(p0.y, q.y, p0.z * q.z));
        float d1 = fmaf(p1.x, q.x, fmaf(p1.y, q.y, p1.z * q.z));
        float d2 = fmaf(p2.x, q.x, fmaf(p2.y, q.y, p2.z * q.z));
        float d3 = fmaf(p3.x, q.x, fmaf(p3.y, q.y, p3.z * q.z));
        b0  = fminf(b0,  fmaf(-2.0f, d0, q.w));
        b1v = fminf(b1v, fmaf(-2.0f, d1, q.w));
        b2v = fminf(b2v, fmaf(-2.0f, d2, q.w));
        b3v = fminf(b3v, fmaf(-2.0f, d3, q.w));
    }
    int base = seg * NMAX;
    g_mpart[chunk][base + i0] = b0 + p0.w;
    if (ok1) g_mpart[chunk][base + i1] = b1v + p1.w;
    if (ok2) g_mpart[chunk][base + i2] = b2v + p2.w;
    if (ok3) g_mpart[chunk][base + i3] = b3v + p3.w;
}

// ---------------------------------------------------------
// stage-1 reduce: grid (NB1, 4 segs); per-block partial stats
// ---------------------------------------------------------
__global__ void __launch_bounds__(256)
reduce1_kernel(int N) {
    __shared__ float sh[8][4];
    const float INV2PI = 0.15915494309189535f;
    int seg = blockIdx.y;
    int per = (N + NB1 - 1) / NB1;
    int n0 = blockIdx.x * per;
    int n1 = min(N, n0 + per);
    int tid = threadIdx.x;
    int lane = tid & 31;
    int warp = tid >> 5;

    float mn = BIGF, mx = -BIGF, s = 0.0f, c = 0.0f;
    for (int n = n0 + tid; n < n1; n += 256) {
        int ia = seg * NMAX + n;
        float w = 0.0f, ms = BIGF;
        #pragma unroll
        for (int ch = 0; ch < WCH; ch++) {
            w += g_wpart[ch][ia];
            ms = fminf(ms, g_mpart[ch][ia]);
        }
        float rm = sqrtf(fmaxf(ms, 0.0f));
        mn = fminf(mn, rm);
        if (w * INV2PI >= 0.99f) { mx = fmaxf(mx, rm); s += rm; c += 1.0f; }
    }
    #pragma unroll
    for (int o = 16; o; o >>= 1) {
        mn = fminf(mn, __shfl_xor_sync(0xffffffffu, mn, o));
        mx = fmaxf(mx, __shfl_xor_sync(0xffffffffu, mx, o));
        s +=           __shfl_xor_sync(0xffffffffu, s,  o);
        c +=           __shfl_xor_sync(0xffffffffu, c,  o);
    }
    if (lane == 0) { sh[warp][0] = mn; sh[warp][1] = mx; sh[warp][2] = s; sh[warp][3] = c; }
    __syncthreads();
    if (tid == 0) {
        #pragma unroll
        for (int w = 1; w < 8; w++) {
            mn = fminf(mn, sh[w][0]);
            mx = fmaxf(mx, sh[w][1]);
            s += sh[w][2];
            c += sh[w][3];
        }
        g_red[seg][blockIdx.x] = make_float4(mn, mx, s, c);
    }
}

// ---------------------------------------------------------
// stage-2 reduce: 4 warps, one per seg; lanes over NB1 blocks
// out layout: [5][B] row-major
// ---------------------------------------------------------
__global__ void __launch_bounds__(128)
reduce2_kernel(float* __restrict__ out) {
    __shared__ float sh[4][4];
    int tid = threadIdx.x;
    int lane = tid & 31;
    int seg = tid >> 5;

    float4 v = g_red[seg][lane];   // NB1 == 32
    float mn = v.x, mx = v.y, s = v.z, c = v.w;
    #pragma unroll
    for (int o = 16; o; o >>= 1) {
        mn = fminf(mn, __shfl_xor_sync(0xffffffffu, mn, o));
        mx = fmaxf(mx, __shfl_xor_sync(0xffffffffu, mx, o));
        s +=           __shfl_xor_sync(0xffffffffu, s,  o);
        c +=           __shfl_xor_sync(0xffffffffu, c,  o);
    }
    if (lane == 0) { sh[seg][0] = mn; sh[seg][1] = mx; sh[seg][2] = s; sh[seg][3] = c; }
    __syncthreads();
    if (tid < B_) {
        int b = tid;
        float mn0 = sh[b][0];
        float mx1 = sh[b][1], s1 = sh[b][2], c1 = sh[b][3];
        float mx2 = sh[2 + b][1], s2 = sh[2 + b][2], c2 = sh[2 + b][3];
        out[0 * B_ + b] = mn0;
        out[1 * B_ + b] = (c1 > 0.0f) ? mx1 : 0.0f;
        out[2 * B_ + b] = (c1 > 0.0f) ? s1 / fmaxf(c1, 1.0f) : 0.0f;
        out[3 * B_ + b] = (c2 > 0.0f) ? mx2 : 0.0f;
        out[4 * B_ + b] = (c2 > 0.0f) ? s2 / fmaxf(c2, 1.0f) : 0.0f;
    }
}

// ---------------------------------------------------------
extern "C" void kernel_launch(void* const* d_in, const int* in_sizes, int n_in,
                              void* d_out, int out_size) {
    const float* v1 = (const float*)d_in[0];
    const float* v2 = (const float*)d_in[1];
    const int* faces = (const int*)d_in[2];
    float* out = (float*)d_out;

    int N = in_sizes[0] / (3 * B_);   // 6890
    int NF = in_sizes[2] / 3;         // 2000

    int gwork = B_ * N;
    if (B_ * NF > gwork) gwork = B_ * NF;
    gather_kernel<<<(gwork + 255) / 256, 256>>>(v1, v2, faces, N, NF);

    int H = (N + 1) >> 1;
    dim3 wgrid((H + 255) / 256, 4 * WCH);
    winding_kernel<<<wgrid, 256>>>(N, NF);

    int Q = (N + 3) >> 2;
    dim3 mgrid((Q + 255) / 256, 4 * MCH);
    minsq_kernel<<<mgrid, 256>>>(N);

    dim3 rgrid(NB1, 4);
    reduce1_kernel<<<rgrid, 256>>>(N);
    reduce2_kernel<<<1, 128>>>(out);
}